// round 7
// baseline (speedup 1.0000x reference)
#include <cuda_runtime.h>

#define Nn    6000
#define DEG   16
#define Mm    17          // DEG + 1
#define NT    16
#define MTt   10
#define NF    128
#define KT    160         // NT * MTt
#define PT    12          // padded per-template chunk
#define TKSTR 204         // per-k T region stride (17 rows x 12)
#define NITER 10
#define THREADS 256       // 8 warps; warp w owns k = 2w, 2w+1
#define GEMM_ROWS 40
#define GEMM_SMEM ((KT * 129 + GEMM_ROWS * NF) * 4)

__device__ float g_G[Nn * KT];
__device__ float g_xn[Nn];
__device__ float g_f2n[KT];

// ---------------------------------------------------------------------------
// packed f32x2 helpers (sm_103a)
// ---------------------------------------------------------------------------
typedef unsigned long long ull;
__device__ __forceinline__ ull pk2(float lo, float hi) {
    ull r;
    asm("mov.b64 %0, {%1, %2};" : "=l"(r) : "f"(lo), "f"(hi));
    return r;
}
__device__ __forceinline__ void upk2(float& lo, float& hi, ull v) {
    asm("mov.b64 {%0, %1}, %2;" : "=f"(lo), "=f"(hi) : "l"(v));
}
__device__ __forceinline__ void ffma2(ull& d, ull a, ull b) {
    asm("fma.rn.f32x2 %0, %1, %2, %0;" : "+l"(d) : "l"(a), "l"(b));
}
__device__ __forceinline__ ull fma2r(ull a, ull b, ull c) {
    ull d;
    asm("fma.rn.f32x2 %0, %1, %2, %3;" : "=l"(d) : "l"(a), "l"(b), "l"(c));
    return d;
}
__device__ __forceinline__ void add2(ull& d, ull a) {
    asm("add.rn.f32x2 %0, %0, %1;" : "+l"(d) : "l"(a));
}
__device__ __forceinline__ void sub2(ull& d, ull a) {
    ull nz = a ^ 0x8000000080000000ULL;
    asm("add.rn.f32x2 %0, %0, %1;" : "+l"(d) : "l"(nz));
}
__device__ __forceinline__ float hadd2(ull v) {
    float lo, hi; upk2(lo, hi, v);
    return lo + hi;
}
// load 12 contiguous floats as 5 packed pairs (elements 0..9)
__device__ __forceinline__ void ld_chunk(ull* v, const float* p) {
    float4 a = *(const float4*)p, b = *(const float4*)(p + 4),
           c = *(const float4*)(p + 8);
    v[0] = pk2(a.x, a.y); v[1] = pk2(a.z, a.w);
    v[2] = pk2(b.x, b.y); v[3] = pk2(b.z, b.w);
    v[4] = pk2(c.x, c.y);
}
// deferred mirror-descent register update
__device__ __forceinline__ void lt_update(ull* ltp, const ull* McBp,
                                          const ull* ccp, const ull* y2p,
                                          ull cA2p, ull ncA4p, ull neg1p) {
    #pragma unroll
    for (int j = 0; j < 5; j++) {
        ull d = fma2r(cA2p, ccp[j], McBp[j]);
        d = fma2r(ncA4p, y2p[j], d);
        ltp[j] = fma2r(d, neg1p, ltp[j]);
    }
}
// softmax over 10 packed values -> T row (scaled by 1/17)
__device__ __forceinline__ void softmax_store(const ull* ltp, float* dstRow) {
    float e[10];
    #pragma unroll
    for (int j = 0; j < 5; j++) upk2(e[2*j], e[2*j+1], ltp[j]);
    float mx = e[0];
    #pragma unroll
    for (int t = 1; t < MTt; t++) mx = fmaxf(mx, e[t]);
    float ssum = 0.f;
    #pragma unroll
    for (int t = 0; t < MTt; t++) { e[t] = __expf(e[t] - mx); ssum += e[t]; }
    float inv = (1.f / (float)Mm) / ssum;
    *(float4*)(dstRow)     = make_float4(e[0]*inv, e[1]*inv, e[2]*inv, e[3]*inv);
    *(float4*)(dstRow + 4) = make_float4(e[4]*inv, e[5]*inv, e[6]*inv, e[7]*inv);
    *(float4*)(dstRow + 8) = make_float4(e[8]*inv, e[9]*inv, 0.f, 0.f);
}

// ---------------------------------------------------------------------------
// Kernel 1: G = x @ F2^T (+ fused row norms)  [unchanged]
// ---------------------------------------------------------------------------
__global__ __launch_bounds__(256, 2)
void gemm_kernel(const float* __restrict__ x, const float* __restrict__ F2) {
    extern __shared__ float sm[];
    float* sF2 = sm;                 // 160 x 129
    float* sX  = sm + KT * 129;      // 40 x 128
    int tid = threadIdx.x;
    int r0 = blockIdx.x * GEMM_ROWS;

    for (int i = tid; i < KT * NF; i += 256) {
        int r = i >> 7, f = i & 127;
        sF2[r * 129 + f] = F2[i];
    }
    for (int i = tid; i < GEMM_ROWS * NF; i += 256)
        sX[i] = x[(size_t)r0 * NF + i];
    __syncthreads();

    if (tid < GEMM_ROWS) {
        float s = 0.f;
        #pragma unroll 8
        for (int f = 0; f < NF; f++) { float v = sX[tid * NF + f]; s += v * v; }
        g_xn[r0 + tid] = s;
    }
    if (blockIdx.x == 0 && tid >= 64 && tid < 64 + KT) {
        int r = tid - 64;
        float s = 0.f;
        #pragma unroll 8
        for (int f = 0; f < NF; f++) { float v = sF2[r * 129 + f]; s += v * v; }
        g_f2n[r] = s;
    }

    int tm = tid >> 5;
    int tn = tid & 31;
    float acc[5][5];
    #pragma unroll
    for (int i = 0; i < 5; i++)
        #pragma unroll
        for (int j = 0; j < 5; j++) acc[i][j] = 0.f;

    for (int f = 0; f < NF; f++) {
        float av[5], bv[5];
        #pragma unroll
        for (int i = 0; i < 5; i++) av[i] = sX[(tm * 5 + i) * NF + f];
        #pragma unroll
        for (int j = 0; j < 5; j++) bv[j] = sF2[(tn * 5 + j) * 129 + f];
        #pragma unroll
        for (int i = 0; i < 5; i++)
            #pragma unroll
            for (int j = 0; j < 5; j++) acc[i][j] += av[i] * bv[j];
    }
    #pragma unroll
    for (int i = 0; i < 5; i++) {
        int row = r0 + tm * 5 + i;
        #pragma unroll
        for (int j = 0; j < 5; j++)
            g_G[(size_t)row * KT + tn * 5 + j] = acc[i][j];
    }
}

// ---------------------------------------------------------------------------
// Kernel 2: barrier-free mirror-descent. Block = node, warp owns 2 templates.
// Lane = [k-half][m-1]; lanes 0/16 also carry row 0 in duplicate registers.
// No __syncthreads in the iteration loop — only __syncwarp.
// ---------------------------------------------------------------------------
struct SmemMain {
    float T   [NT * TKSTR];   // 16 regions of 17 rows x 12 (16B-aligned rows)
    float C2  [NT * MTt * PT];
    float C2sq[NT * MTt * PT];
    float q   [NT * PT];
    float cc  [NT * PT];
    float c1p[Mm];
    float xnl[Mm];
    int   nbrs[Mm];
    int   dstl[Mm * DEG];
    unsigned mask[Mm];
};

__global__ __launch_bounds__(THREADS, 2)
void main_kernel(const int* __restrict__ dst, const float* __restrict__ C2g,
                 const float* __restrict__ alpha0, float* __restrict__ out) {
    extern __shared__ char smraw[];
    SmemMain& s = *reinterpret_cast<SmemMain*>(smraw);
    int n = blockIdx.x, tid = threadIdx.x;
    int w = tid >> 5, lane = tid & 31;
    int hf = lane >> 4, sub = lane & 15;
    int k = 2 * w + hf;
    int m = sub + 1;
    bool lead = (sub == 0);

    float a0 = alpha0[0];
    float alpha = 1.f / (1.f + __expf(-a0));
    float coefA = alpha * 10.f;
    float coefM = (1.f - alpha) * 10.f;
    float cA2 = 2.f * coefA, cA4 = 4.f * coefA;
    ull cA2p = pk2(cA2, cA2);
    ull ncA4p = pk2(-cA4, -cA4);
    ull neg1p = pk2(-1.f, -1.f);

    // --- staging ---
    if (tid < Mm) s.nbrs[tid] = (tid == 0) ? n : dst[n * DEG + tid - 1];
    for (int i = tid; i < NT * MTt * PT; i += THREADS) {
        int kt = i / PT, col = i - kt * PT;
        float v = (col < MTt) ? C2g[kt * MTt + col] : 0.f;
        s.C2[i] = v;
        s.C2sq[i] = v * v;
    }
    __syncthreads();
    for (int i = tid; i < Mm * DEG; i += THREADS)
        s.dstl[i] = dst[s.nbrs[i >> 4] * DEG + (i & 15)];
    __syncthreads();

    if (tid < Mm) {
        int me = s.nbrs[tid];
        unsigned mrow = 0;
        for (int b = 0; b < Mm; b++) {
            int nb = s.nbrs[b];
            bool adj = false;
            #pragma unroll
            for (int j = 0; j < DEG; j++)
                adj = adj || (s.dstl[tid * DEG + j] == nb) ||
                             (s.dstl[b   * DEG + j] == me);
            if (adj) mrow |= (1u << b);
        }
        s.mask[tid] = mrow;
        s.c1p[tid]  = (float)__popc(mrow) * (1.f / (float)Mm);
        s.xnl[tid]  = g_xn[me];
    }
    __syncthreads();

    // --- per-thread persistent state ---
    float* Tk = &s.T[k * TKSTR];
    float* Trow = Tk + m * PT;
    unsigned msk_m = s.mask[m];
    unsigned extras = msk_m & ~1u;       // bit 0 always set for m>=1
    unsigned mask0 = s.mask[0];
    const bool ccOwn = (sub >= 1 && sub <= MTt);   // computes cc[k][sub-1]

    ull ltp[5], McBp[5], lt0p[5], McB0p[5];
    {
        float xn = s.xnl[m];
        float cpv = cA2 * s.c1p[m];
        const float* Grow = g_G + (size_t)s.nbrs[m] * KT + k * MTt;
        const float* f2p  = g_f2n + k * MTt;
        #pragma unroll
        for (int j = 0; j < 5; j++) {
            float a = coefM * (xn + f2p[2*j]   - 2.f * __ldg(Grow + 2*j))   + cpv;
            float b = coefM * (xn + f2p[2*j+1] - 2.f * __ldg(Grow + 2*j+1)) + cpv;
            McBp[j] = pk2(a, b);
            ltp[j] = 0ULL;
        }
        if (lead) {
            float xn0 = s.xnl[0];
            float cpv0 = cA2 * s.c1p[0];
            const float* G0 = g_G + (size_t)n * KT + k * MTt;
            #pragma unroll
            for (int j = 0; j < 5; j++) {
                float a = coefM * (xn0 + f2p[2*j]   - 2.f * __ldg(G0 + 2*j))   + cpv0;
                float b = coefM * (xn0 + f2p[2*j+1] - 2.f * __ldg(G0 + 2*j+1)) + cpv0;
                McB0p[j] = pk2(a, b);
                lt0p[j] = 0ULL;
            }
        }
    }
    __syncthreads();   // last block barrier: T/C2 regions ready, state built

    ull ccp[5], y2p[5], y20p[5];
    #pragma unroll
    for (int j = 0; j < 5; j++) { ccp[j] = 0ULL; y2p[j] = 0ULL; y20p[j] = 0ULL; }

    for (int it = 0; it < NITER; it++) {
        // A) deferred update + softmax -> T (lead also does row 0)
        if (it > 0) {
            lt_update(ltp, McBp, ccp, y2p, cA2p, ncA4p, neg1p);
            if (lead) lt_update(lt0p, McB0p, ccp, y20p, cA2p, ncA4p, neg1p);
        }
        softmax_store(ltp, Trow);
        if (lead) softmax_store(lt0p, Tk);
        __syncwarp();

        // B) q colsums (sub<10, both halves in one instruction stream)
        //    + sparse y1 gather for row m
        if (sub < MTt) {
            float acc = 0.f;
            #pragma unroll
            for (int mm = 0; mm < Mm; mm++) acc += Tk[mm * PT + sub];
            s.q[k * PT + sub] = acc;
        }
        ull y1p[5];
        ld_chunk(y1p, Tk);                 // T row 0 (bit 0 always set)
        {
            unsigned msk = extras;         // rare extra neighbors
            while (msk) {
                int b = __ffs(msk) - 1;
                msk &= msk - 1;
                ull ex[5];
                ld_chunk(ex, Tk + b * PT);
                #pragma unroll
                for (int j = 0; j < 5; j++) add2(y1p[j], ex[j]);
            }
        }
        __syncwarp();

        // C) cc (lanes sub=1..10) || lead row-0 y1 from q || y2 dots
        if (ccOwn) {
            int ss = sub - 1;
            ull qc[5], sc[5];
            ld_chunk(qc, &s.q[k * PT]);
            ld_chunk(sc, &s.C2sq[(k * MTt + ss) * PT]);
            ull acc = 0ULL;
            #pragma unroll
            for (int j = 0; j < 5; j++) ffma2(acc, qc[j], sc[j]);
            s.cc[k * PT + ss] = hadd2(acc);
        }
        float y[10], y0[10];
        #pragma unroll
        for (int j = 0; j < 5; j++) upk2(y[2*j], y[2*j+1], y1p[j]);
        if (lead) {
            ull y10p[5];
            ld_chunk(y10p, &s.q[k * PT]);          // y1_0 = q ...
            if (!(mask0 & 1u)) {                   // ... minus T0 if no self-loop
                ull t0[5];
                ld_chunk(t0, Tk);
                #pragma unroll
                for (int j = 0; j < 5; j++) sub2(y10p[j], t0[j]);
            }
            #pragma unroll
            for (int j = 0; j < 5; j++) upk2(y0[2*j], y0[2*j+1], y10p[j]);
        }
        #pragma unroll
        for (int j = 0; j < 5; j++) { y2p[j] = 0ULL; y20p[j] = 0ULL; }
        #pragma unroll
        for (int t = 0; t < MTt; t++) {
            ull rp[5];
            ld_chunk(rp, &s.C2[(k * MTt + t) * PT]);   // broadcast (2 addr/warp)
            ull yt = pk2(y[t], y[t]);
            #pragma unroll
            for (int j = 0; j < 5; j++) ffma2(y2p[j], yt, rp[j]);
            if (lead) {
                ull yt0 = pk2(y0[t], y0[t]);
                #pragma unroll
                for (int j = 0; j < 5; j++) ffma2(y20p[j], yt0, rp[j]);
            }
        }
        __syncwarp();

        // D) read cc chunk (shared by row 0 and rows 1..16)
        ld_chunk(ccp, &s.cc[k * PT]);
    }

    // --- final update + softmax -> T, then output marginals ---
    lt_update(ltp, McBp, ccp, y2p, cA2p, ncA4p, neg1p);
    softmax_store(ltp, Trow);
    if (lead) {
        lt_update(lt0p, McB0p, ccp, y20p, cA2p, ncA4p, neg1p);
        softmax_store(lt0p, Tk);
    }
    __syncwarp();
    if (sub < MTt) {
        float acc = 0.f;
        #pragma unroll
        for (int mm = 0; mm < Mm; mm++) acc += Tk[mm * PT + sub];
        out[(size_t)n * KT + k * MTt + sub] = acc;
    }
}

// ---------------------------------------------------------------------------
extern "C" void kernel_launch(void* const* d_in, const int* in_sizes, int n_in,
                              void* d_out, int out_size) {
    const float* x   = (const float*)d_in[0];
    const int*   ei  = (const int*)d_in[1];
    const float* C2g = (const float*)d_in[2];
    const float* F2  = (const float*)d_in[3];
    const float* a0  = (const float*)d_in[4];
    float* out = (float*)d_out;
    const int* dst = ei + Nn * DEG;

    cudaFuncSetAttribute(gemm_kernel, cudaFuncAttributeMaxDynamicSharedMemorySize,
                         GEMM_SMEM);
    cudaFuncSetAttribute(main_kernel, cudaFuncAttributeMaxDynamicSharedMemorySize,
                         (int)sizeof(SmemMain));

    gemm_kernel<<<Nn / GEMM_ROWS, 256, GEMM_SMEM>>>(x, F2);
    main_kernel<<<Nn, THREADS, sizeof(SmemMain)>>>(dst, C2g, a0, out);
}

// round 11
// speedup vs baseline: 1.9488x; 1.9488x over previous
#include <cuda_runtime.h>

#define Nn    6000
#define DEG   16
#define Mm    17          // DEG + 1
#define NT    16
#define MTt   10
#define NF    128
#define KT    160         // NT * MTt
#define PT    12          // padded per-template chunk
#define TKSTR 204         // per-k T region stride (17 rows x 12)
#define NITER 10
#define THREADS 256       // 8 warps; warp w owns k = 2w, 2w+1
#define GEMM_ROWS 40
#define GEMM_SMEM ((KT * 129 + GEMM_ROWS * NF) * 4)

__device__ float g_G[Nn * KT];
__device__ float g_xn[Nn];
__device__ float g_f2n[KT];

// ---------------------------------------------------------------------------
// packed f32x2 helpers (sm_103a)
// ---------------------------------------------------------------------------
typedef unsigned long long ull;
__device__ __forceinline__ ull pk2(float lo, float hi) {
    ull r;
    asm("mov.b64 %0, {%1, %2};" : "=l"(r) : "f"(lo), "f"(hi));
    return r;
}
__device__ __forceinline__ void upk2(float& lo, float& hi, ull v) {
    asm("mov.b64 {%0, %1}, %2;" : "=f"(lo), "=f"(hi) : "l"(v));
}
__device__ __forceinline__ void ffma2(ull& d, ull a, ull b) {
    asm("fma.rn.f32x2 %0, %1, %2, %0;" : "+l"(d) : "l"(a), "l"(b));
}
__device__ __forceinline__ ull fma2r(ull a, ull b, ull c) {
    ull d;
    asm("fma.rn.f32x2 %0, %1, %2, %3;" : "=l"(d) : "l"(a), "l"(b), "l"(c));
    return d;
}
__device__ __forceinline__ ull mul2r(ull a, ull b) {
    ull d;
    asm("mul.rn.f32x2 %0, %1, %2;" : "=l"(d) : "l"(a), "l"(b));
    return d;
}
__device__ __forceinline__ void add2(ull& d, ull a) {
    asm("add.rn.f32x2 %0, %0, %1;" : "+l"(d) : "l"(a));
}
__device__ __forceinline__ void sub2(ull& d, ull a) {
    ull nz = a ^ 0x8000000080000000ULL;
    asm("add.rn.f32x2 %0, %0, %1;" : "+l"(d) : "l"(nz));
}
__device__ __forceinline__ float hadd2(ull v) {
    float lo, hi; upk2(lo, hi, v);
    return lo + hi;
}
__device__ __forceinline__ void ld_chunk(ull* v, const float* p) {
    float4 a = *(const float4*)p, b = *(const float4*)(p + 4),
           c = *(const float4*)(p + 8);
    v[0] = pk2(a.x, a.y); v[1] = pk2(a.z, a.w);
    v[2] = pk2(b.x, b.y); v[3] = pk2(b.z, b.w);
    v[4] = pk2(c.x, c.y);
}
__device__ __forceinline__ void lt_update(ull* ltp, const ull* McBp,
                                          const ull* ccp, const ull* y2p,
                                          ull cA2p, ull ncA4p, ull neg1p) {
    #pragma unroll
    for (int j = 0; j < 5; j++) {
        ull d = fma2r(cA2p, ccp[j], McBp[j]);
        d = fma2r(ncA4p, y2p[j], d);
        ltp[j] = fma2r(d, neg1p, ltp[j]);
    }
}
__device__ __forceinline__ void softmax_store(const ull* ltp, float* dstRow) {
    float e[10];
    #pragma unroll
    for (int j = 0; j < 5; j++) upk2(e[2*j], e[2*j+1], ltp[j]);
    float mx = e[0];
    #pragma unroll
    for (int t = 1; t < MTt; t++) mx = fmaxf(mx, e[t]);
    float ssum = 0.f;
    #pragma unroll
    for (int t = 0; t < MTt; t++) { e[t] = __expf(e[t] - mx); ssum += e[t]; }
    float inv = (1.f / (float)Mm) / ssum;
    *(float4*)(dstRow)     = make_float4(e[0]*inv, e[1]*inv, e[2]*inv, e[3]*inv);
    *(float4*)(dstRow + 4) = make_float4(e[4]*inv, e[5]*inv, e[6]*inv, e[7]*inv);
    *(float4*)(dstRow + 8) = make_float4(e[8]*inv, e[9]*inv, 0.f, 0.f);
}

// ---------------------------------------------------------------------------
// Kernel 1: G = x @ F2^T (+ fused row norms)
// ---------------------------------------------------------------------------
__global__ __launch_bounds__(256, 2)
void gemm_kernel(const float* __restrict__ x, const float* __restrict__ F2) {
    extern __shared__ float sm[];
    float* sF2 = sm;                 // 160 x 129
    float* sX  = sm + KT * 129;      // 40 x 128
    int tid = threadIdx.x;
    int r0 = blockIdx.x * GEMM_ROWS;

    for (int i = tid; i < KT * NF; i += 256) {
        int r = i >> 7, f = i & 127;
        sF2[r * 129 + f] = F2[i];
    }
    for (int i = tid; i < GEMM_ROWS * NF; i += 256)
        sX[i] = x[(size_t)r0 * NF + i];
    __syncthreads();

    if (tid < GEMM_ROWS) {
        float s = 0.f;
        #pragma unroll 8
        for (int f = 0; f < NF; f++) { float v = sX[tid * NF + f]; s += v * v; }
        g_xn[r0 + tid] = s;
    }
    if (blockIdx.x == 0 && tid >= 64 && tid < 64 + KT) {
        int r = tid - 64;
        float s = 0.f;
        #pragma unroll 8
        for (int f = 0; f < NF; f++) { float v = sF2[r * 129 + f]; s += v * v; }
        g_f2n[r] = s;
    }

    int tm = tid >> 5;
    int tn = tid & 31;
    float acc[5][5];
    #pragma unroll
    for (int i = 0; i < 5; i++)
        #pragma unroll
        for (int j = 0; j < 5; j++) acc[i][j] = 0.f;

    for (int f = 0; f < NF; f++) {
        float av[5], bv[5];
        #pragma unroll
        for (int i = 0; i < 5; i++) av[i] = sX[(tm * 5 + i) * NF + f];
        #pragma unroll
        for (int j = 0; j < 5; j++) bv[j] = sF2[(tn * 5 + j) * 129 + f];
        #pragma unroll
        for (int i = 0; i < 5; i++)
            #pragma unroll
            for (int j = 0; j < 5; j++) acc[i][j] += av[i] * bv[j];
    }
    #pragma unroll
    for (int i = 0; i < 5; i++) {
        int row = r0 + tm * 5 + i;
        #pragma unroll
        for (int j = 0; j < 5; j++)
            g_G[(size_t)row * KT + tn * 5 + j] = acc[i][j];
    }
}

// ---------------------------------------------------------------------------
// Kernel 2: barrier-free mirror-descent, row 0 distributed across lanes.
// Warp w owns k = 2w, 2w+1. Lane = [half][sub]; row m = sub+1 per lane;
// row 0: lane sub<10 holds lt0[t=sub] as a scalar (softmax via shuffles).
// ---------------------------------------------------------------------------
struct SmemMain {
    float T  [NT * TKSTR];    // 16 regions x (17 rows x 12)
    float C2 [NT * MTt * PT]; // rows padded to 12, pads zero
    float q  [NT * PT];
    float cc [NT * PT];
    float c1p[Mm];
    float xnl[Mm];
    int   nbrs[Mm];
    int   dstl[Mm * DEG];
    unsigned mask[Mm];
};

__global__ __launch_bounds__(THREADS, 3)
void main_kernel(const int* __restrict__ dst, const float* __restrict__ C2g,
                 const float* __restrict__ alpha0, float* __restrict__ out) {
    extern __shared__ char smraw[];
    SmemMain& s = *reinterpret_cast<SmemMain*>(smraw);
    int n = blockIdx.x, tid = threadIdx.x;
    int w = tid >> 5, lane = tid & 31;
    int hf = lane >> 4, sub = lane & 15;
    int k = 2 * w + hf;
    int m = sub + 1;
    const float NEG_INF = __int_as_float(0xff800000);

    float a0 = alpha0[0];
    float alpha = 1.f / (1.f + __expf(-a0));
    float coefA = alpha * 10.f;
    float coefM = (1.f - alpha) * 10.f;
    float cA2 = 2.f * coefA, cA4 = 4.f * coefA;
    ull cA2p = pk2(cA2, cA2);
    ull ncA4p = pk2(-cA4, -cA4);
    ull neg1p = pk2(-1.f, -1.f);

    // --- prologue (parallel) ---
    if (tid < Mm) {
        s.nbrs[tid] = (tid == 0) ? n : dst[n * DEG + tid - 1];
        s.mask[tid] = 0u;
    }
    __syncthreads();
    for (int i = tid; i < Mm * DEG; i += THREADS)
        s.dstl[i] = dst[s.nbrs[i >> 4] * DEG + (i & 15)];
    for (int i = tid; i < NT * MTt * PT; i += THREADS) {
        int row = i / PT, col = i - row * PT;
        s.C2[i] = (col < MTt) ? C2g[row * MTt + col] : 0.f;
    }
    __syncthreads();
    for (int i = tid; i < Mm * Mm; i += THREADS) {
        int a = i / Mm, b = i - a * Mm;
        int me = s.nbrs[a], nb = s.nbrs[b];
        bool adj = false;
        #pragma unroll
        for (int j = 0; j < DEG; j++)
            adj = adj || (s.dstl[a * DEG + j] == nb) ||
                         (s.dstl[b * DEG + j] == me);
        if (adj) atomicOr(&s.mask[a], 1u << b);
    }
    __syncthreads();
    if (tid < Mm) {
        s.c1p[tid] = (float)__popc(s.mask[tid]) * (1.f / (float)Mm);
        s.xnl[tid] = g_xn[s.nbrs[tid]];
    }
    __syncthreads();

    // --- per-thread persistent state ---
    float* Tk = &s.T[k * TKSTR];
    float* Trow = Tk + m * PT;
    unsigned extras = s.mask[m] & ~1u;   // bit 0 always set for m>=1
    bool diag0 = (s.mask[0] & 1u) != 0;

    ull ltp[5], McBp[5];
    float lt0, McB0;
    {
        float xn = s.xnl[m];
        float cpv = cA2 * s.c1p[m];
        const float* Grow = g_G + (size_t)s.nbrs[m] * KT + k * MTt;
        const float* f2p  = g_f2n + k * MTt;
        #pragma unroll
        for (int j = 0; j < 5; j++) {
            float a = coefM * (xn + f2p[2*j]   - 2.f * __ldg(Grow + 2*j))   + cpv;
            float b = coefM * (xn + f2p[2*j+1] - 2.f * __ldg(Grow + 2*j+1)) + cpv;
            McBp[j] = pk2(a, b);
            ltp[j] = 0ULL;
        }
        int t0i = (sub < MTt) ? sub : 9;
        McB0 = coefM * (s.xnl[0] + f2p[t0i]
                        - 2.f * __ldg(g_G + (size_t)n * KT + k * MTt + t0i))
             + cA2 * s.c1p[0];
        lt0 = (sub < MTt) ? 0.f : NEG_INF;
    }
    __syncthreads();   // last block barrier

    for (int it = 0; it <= NITER; it++) {
        // A) softmax rows 1..16 -> T rows; row 0 via half-warp shuffles
        softmax_store(ltp, Trow);
        {
            float mx0 = lt0;
            #pragma unroll
            for (int d = 1; d < 16; d <<= 1)
                mx0 = fmaxf(mx0, __shfl_xor_sync(0xffffffffu, mx0, d));
            float e0 = __expf(lt0 - mx0);
            float ss0 = e0;
            #pragma unroll
            for (int d = 1; d < 16; d <<= 1)
                ss0 += __shfl_xor_sync(0xffffffffu, ss0, d);
            if (sub < MTt) Tk[sub] = e0 * ((1.f / (float)Mm) / ss0);
        }
        __syncwarp();
        if (it == NITER) break;

        // B) q colsums (lanes sub<10) + y1 gather + y2 dots (rows)
        if (sub < MTt) {
            float acc = 0.f;
            #pragma unroll
            for (int mm = 0; mm < Mm; mm++) acc += Tk[mm * PT + sub];
            s.q[k * PT + sub] = acc;
        }
        ull y1p[5];
        ld_chunk(y1p, Tk);             // row 0 (bit 0 always set)
        {
            unsigned msk = extras;     // rare extra neighbors
            while (msk) {
                int b = __ffs(msk) - 1;
                msk &= msk - 1;
                ull ex[5];
                ld_chunk(ex, Tk + b * PT);
                #pragma unroll
                for (int j = 0; j < 5; j++) add2(y1p[j], ex[j]);
            }
        }
        float y[10];
        #pragma unroll
        for (int j = 0; j < 5; j++) upk2(y[2*j], y[2*j+1], y1p[j]);
        ull y2p[5];
        #pragma unroll
        for (int j = 0; j < 5; j++) y2p[j] = 0ULL;
        #pragma unroll
        for (int t = 0; t < MTt; t++) {
            ull rp[5];
            ld_chunk(rp, &s.C2[(k * MTt + t) * PT]);  // 2 addrs/warp (broadcast)
            ull yt = pk2(y[t], y[t]);
            #pragma unroll
            for (int j = 0; j < 5; j++) ffma2(y2p[j], yt, rp[j]);
        }
        __syncwarp();

        // C) lanes sub<10: cc[k][sub] + row-0 y2/update (shares the C2 row)
        if (sub < MTt) {
            ull qc[5], cr[5];
            ld_chunk(qc, &s.q[k * PT]);
            ld_chunk(cr, &s.C2[(k * MTt + sub) * PT]);
            ull y1c[5];
            #pragma unroll
            for (int j = 0; j < 5; j++) y1c[j] = qc[j];
            if (!diag0) {              // y1_0 = q - T0 (unless self-loop)
                ull t0c[5];
                ld_chunk(t0c, Tk);
                #pragma unroll
                for (int j = 0; j < 5; j++) sub2(y1c[j], t0c[j]);
            }
            ull cacc = 0ULL, yacc = 0ULL;
            #pragma unroll
            for (int j = 0; j < 5; j++) {
                ull sq = mul2r(cr[j], cr[j]);
                ffma2(cacc, qc[j], sq);        // constC2
                ffma2(yacc, y1c[j], cr[j]);    // y2 row 0
            }
            float cc_s = hadd2(cacc);
            float y20_s = hadd2(yacc);
            s.cc[k * PT + sub] = cc_s;
            lt0 -= (McB0 + cA2 * cc_s - cA4 * y20_s);
        }
        __syncwarp();

        // D) rows update from cc chunk
        ull ccp[5];
        ld_chunk(ccp, &s.cc[k * PT]);
        lt_update(ltp, McBp, ccp, y2p, cA2p, ncA4p, neg1p);
    }

    // --- output marginals ---
    if (sub < MTt) {
        float acc = 0.f;
        #pragma unroll
        for (int mm = 0; mm < Mm; mm++) acc += Tk[mm * PT + sub];
        out[(size_t)n * KT + k * MTt + sub] = acc;
    }
}

// ---------------------------------------------------------------------------
extern "C" void kernel_launch(void* const* d_in, const int* in_sizes, int n_in,
                              void* d_out, int out_size) {
    const float* x   = (const float*)d_in[0];
    const int*   ei  = (const int*)d_in[1];
    const float* C2g = (const float*)d_in[2];
    const float* F2  = (const float*)d_in[3];
    const float* a0  = (const float*)d_in[4];
    float* out = (float*)d_out;
    const int* dst = ei + Nn * DEG;

    cudaFuncSetAttribute(gemm_kernel, cudaFuncAttributeMaxDynamicSharedMemorySize,
                         GEMM_SMEM);
    cudaFuncSetAttribute(main_kernel, cudaFuncAttributeMaxDynamicSharedMemorySize,
                         (int)sizeof(SmemMain));

    gemm_kernel<<<Nn / GEMM_ROWS, 256, GEMM_SMEM>>>(x, F2);
    main_kernel<<<Nn, THREADS, sizeof(SmemMain)>>>(dst, C2g, a0, out);
}